// round 2
// baseline (speedup 1.0000x reference)
#include <cuda_runtime.h>
#include <math.h>

#define NB 2
#define NV 6
#define NC 256
#define NQ 900
#define NM (NB*NQ)       // 1800 rows
#define NH 8
#define HDIM 32

#define NEG_INF (__int_as_float(0xff800000))

// Scratch (no allocations allowed)
__device__ float g_ctx[NM*NC];
__device__ float g_q[NM*NC];
__device__ float g_k[NM*NC];
__device__ float g_v[NM*NC];
__device__ float g_o[NM*NC];

// ---------------------------------------------------------------------------
// Sampler: one block per (b,q). 48 projections (2 levels x 6 views x 4 kps)
// set up by threads 0..47; then 256 threads (one per channel) gather only
// in-bounds taps. Validity count (z>0) matches reference exactly.
// ---------------------------------------------------------------------------
__global__ __launch_bounds__(256) void sampler_kernel(
    const float* __restrict__ f0, const float* __restrict__ f1,
    const float* __restrict__ refs, const float* __restrict__ intr,
    const float* __restrict__ extr)
{
    const int q = blockIdx.x, b = blockIdx.y;
    __shared__ int   s_off[48][4];
    __shared__ float s_w[48][4];
    __shared__ int   s_valid[48];
    __shared__ int   s_any[48];
    const int t = threadIdx.x;

    if (t < 48) {
        const int lvl = t / 24, rem = t % 24, v = rem >> 2, kp = rem & 3;
        const float kxs[4] = {0.f, 2.f, 0.f, -2.f};
        const float kys[4] = {0.f, 0.f, 2.f, 0.f};
        const float* rp = refs + ((size_t)b*NQ + q)*3;
        float px = rp[0] + kxs[kp], py = rp[1] + kys[kp], pz = rp[2];
        const float* E = extr + ((size_t)b*NV + v)*16;
        float cx = E[0]*px + E[1]*py + E[2]*pz  + E[3];
        float cy = E[4]*px + E[5]*py + E[6]*pz  + E[7];
        float cz = E[8]*px + E[9]*py + E[10]*pz + E[11];
        const float* I = intr + ((size_t)b*NV + v)*9;
        float u  = I[0]*cx + I[1]*cy + I[2]*cz;
        float vv = I[3]*cx + I[4]*cy + I[5]*cz;
        float w  = I[6]*cx + I[7]*cy + I[8]*cz;
        float zs = (fabsf(w) > 1e-6f) ? w : 1e-6f;
        const int Wd = lvl ? 88 : 176, Hd = lvl ? 32 : 64;
        // replicate reference's normalize->denormalize round trip exactly
        float gx = 2.f*(u/zs)/(float)(Wd-1) - 1.f;
        float gy = 2.f*(vv/zs)/(float)(Hd-1) - 1.f;
        float x = (gx + 1.f)*0.5f*(float)(Wd-1);
        float y = (gy + 1.f)*0.5f*(float)(Hd-1);
        float x0 = floorf(x), y0 = floorf(y);
        float wx1 = x - x0, wx0 = 1.f - wx1;
        float wy1 = y - y0, wy0 = 1.f - wy1;
        const int valid = (w > 0.f) ? 1 : 0;
        s_valid[t] = valid;
        int any = 0;
        #pragma unroll
        for (int ti = 0; ti < 4; ti++) {
            float xi = (ti & 1) ? x0 + 1.f : x0;
            float yi = (ti & 2) ? y0 + 1.f : y0;
            float wt = ((ti & 1) ? wx1 : wx0) * ((ti & 2) ? wy1 : wy0);
            bool inb = (xi >= 0.f) && (xi <= (float)(Wd-1)) &&
                       (yi >= 0.f) && (yi <= (float)(Hd-1));
            if (valid && inb && wt != 0.f) {
                s_off[t][ti] = (int)yi * Wd + (int)xi;
                s_w[t][ti]   = wt;
                any = 1;
            } else {
                s_off[t][ti] = -1;
            }
        }
        s_any[t] = any;
    }
    __syncthreads();

    float acc0 = 0.f, acc1 = 0.f;
    for (int p = 0; p < 48; p++) {
        if (!s_any[p]) continue;
        const int lvl = (p >= 24) ? 1 : 0;
        const int rem = p - lvl*24, v = rem >> 2;
        const float* fb = lvl ? f1 + ((size_t)((b*NV + v)*NC + t))*(32*88)
                              : f0 + ((size_t)((b*NV + v)*NC + t))*(64*176);
        float a = 0.f;
        #pragma unroll
        for (int ti = 0; ti < 4; ti++) {
            int off = s_off[p][ti];
            if (off >= 0) a += s_w[p][ti] * __ldg(fb + off);
        }
        if (lvl) acc1 += a; else acc0 += a;
    }
    int cnt0 = 0, cnt1 = 0;
    #pragma unroll
    for (int p = 0; p < 24; p++) cnt0 += s_valid[p];
    #pragma unroll
    for (int p = 24; p < 48; p++) cnt1 += s_valid[p];
    float r = 0.5f * (acc0 / fmaxf((float)cnt0, 1.f) +
                      acc1 / fmaxf((float)cnt1, 1.f));
    g_ctx[((size_t)b*NQ + q)*NC + t] = r;
}

// ---------------------------------------------------------------------------
// GEMM (NT): C[M,256] = A[M,256] * W[256,256]^T + bias.  64x64x16 tiles,
// 256 threads, 4x4 register micro-tiles.
// ---------------------------------------------------------------------------
__global__ __launch_bounds__(256) void gemm_nt_kernel(
    const float* __restrict__ A, const float* __restrict__ Wm,
    const float* __restrict__ bias, float* __restrict__ C, int M)
{
    const int K = 256, N = 256;
    __shared__ float As[16][64];
    __shared__ float Ws[16][64];
    const int t = threadIdx.x;
    const int tx = t & 15, ty = t >> 4;
    const int m0 = blockIdx.y * 64, n0 = blockIdx.x * 64;
    const int lr = t >> 2, ls = t & 3;

    float acc[4][4] = {};
    for (int k0 = 0; k0 < K; k0 += 16) {
        float4 av = make_float4(0.f, 0.f, 0.f, 0.f);
        if (m0 + lr < M)
            av = *(const float4*)(A + (size_t)(m0 + lr)*K + k0 + ls*4);
        float4 wv = *(const float4*)(Wm + (size_t)(n0 + lr)*K + k0 + ls*4);
        __syncthreads();
        As[ls*4+0][lr] = av.x; As[ls*4+1][lr] = av.y;
        As[ls*4+2][lr] = av.z; As[ls*4+3][lr] = av.w;
        Ws[ls*4+0][lr] = wv.x; Ws[ls*4+1][lr] = wv.y;
        Ws[ls*4+2][lr] = wv.z; Ws[ls*4+3][lr] = wv.w;
        __syncthreads();
        #pragma unroll
        for (int kk = 0; kk < 16; kk++) {
            float a[4], w[4];
            *(float4*)a = *(const float4*)&As[kk][ty*4];
            *(float4*)w = *(const float4*)&Ws[kk][tx*4];
            #pragma unroll
            for (int i = 0; i < 4; i++)
                #pragma unroll
                for (int j = 0; j < 4; j++)
                    acc[i][j] += a[i]*w[j];
        }
    }
    #pragma unroll
    for (int i = 0; i < 4; i++) {
        int m = m0 + ty*4 + i;
        if (m >= M) continue;
        #pragma unroll
        for (int j = 0; j < 4; j++) {
            int n = n0 + tx*4 + j;
            C[(size_t)m*N + n] = acc[i][j] + bias[n];
        }
    }
}

// ---------------------------------------------------------------------------
// Attention: block = 32 q-rows x 4 key-splits (128 thr). K/V staged in smem,
// 64-key tiles, per-tile max + single rescale (online softmax), then a
// 4-way split merge through shared memory.
// ---------------------------------------------------------------------------
__global__ __launch_bounds__(128) void attn_kernel(
    const float* __restrict__ gq, const float* __restrict__ gk,
    const float* __restrict__ gv, float* __restrict__ go)
{
    const int D = NC;
    const float scale = 0.17677669529663687f;   // 1/sqrt(32)
    const int b = blockIdx.z, h = blockIdx.y;
    const int m0 = blockIdx.x * 32;
    const int tid = threadIdx.x;
    const int lane = tid & 31, wrp = tid >> 5;
    const int m = m0 + lane;
    const bool act = (m < NQ);

    __shared__ float sk[64][32];
    __shared__ float sv[64][32];
    __shared__ float s_m[4][32];
    __shared__ float s_l[4][32];
    __shared__ float s_o[4][32][33];   // padded: conflict-free merge

    float qreg[HDIM];
    #pragma unroll
    for (int d = 0; d < HDIM; d++)
        qreg[d] = act ? gq[((size_t)(b*NQ + m))*D + h*HDIM + d] : 0.f;

    float mx = NEG_INF, l = 0.f;
    float o[HDIM];
    #pragma unroll
    for (int d = 0; d < HDIM; d++) o[d] = 0.f;

    for (int k0 = 0; k0 < NQ; k0 += 64) {
        const int kn = min(64, NQ - k0);
        __syncthreads();
        for (int i = tid; i < 512; i += 128) {
            int r = i >> 3, sg = i & 7;
            float4 kv = make_float4(0.f,0.f,0.f,0.f);
            float4 vv = make_float4(0.f,0.f,0.f,0.f);
            if (r < kn) {
                size_t base = ((size_t)(b*NQ + k0 + r))*D + h*HDIM + sg*4;
                kv = *(const float4*)(gk + base);
                vv = *(const float4*)(gv + base);
            }
            *(float4*)&sk[r][sg*4] = kv;
            *(float4*)&sv[r][sg*4] = vv;
        }
        __syncthreads();

        float sc[16];
        float tmax = NEG_INF;
        #pragma unroll
        for (int jj = 0; jj < 16; jj++) {
            int j = wrp*16 + jj;
            float s;
            if (j < kn) {
                s = 0.f;
                #pragma unroll
                for (int d = 0; d < HDIM; d++) s += qreg[d]*sk[j][d];
                s *= scale;
            } else {
                s = NEG_INF;
            }
            sc[jj] = s;
            tmax = fmaxf(tmax, s);
        }
        float mnew = fmaxf(mx, tmax);
        float corr = __expf(mx - mnew);       // exp(-inf)=0 on first tile
        l *= corr;
        #pragma unroll
        for (int d = 0; d < HDIM; d++) o[d] *= corr;
        #pragma unroll
        for (int jj = 0; jj < 16; jj++) {
            int j = wrp*16 + jj;
            float p = __expf(sc[jj] - mnew);
            l += p;
            #pragma unroll
            for (int d = 0; d < HDIM; d++) o[d] += p * sv[j][d];
        }
        mx = mnew;
    }

    // merge the 4 key-splits
    s_m[wrp][lane] = mx;
    s_l[wrp][lane] = l;
    #pragma unroll
    for (int d = 0; d < HDIM; d++) s_o[wrp][lane][d] = o[d];
    __syncthreads();

    if (wrp == 0 && act) {
        float M2 = s_m[0][lane];
        #pragma unroll
        for (int s = 1; s < 4; s++) M2 = fmaxf(M2, s_m[s][lane]);
        float L = 0.f;
        float out[HDIM];
        #pragma unroll
        for (int d = 0; d < HDIM; d++) out[d] = 0.f;
        #pragma unroll
        for (int s = 0; s < 4; s++) {
            float w = __expf(s_m[s][lane] - M2);
            L += s_l[s][lane] * w;
            #pragma unroll
            for (int d = 0; d < HDIM; d++) out[d] += w * s_o[s][lane][d];
        }
        float invL = 1.f / L;
        #pragma unroll
        for (int d = 0; d < HDIM; d++)
            go[((size_t)(b*NQ + m))*D + h*HDIM + d] = out[d] * invL;
    }
}

// ---------------------------------------------------------------------------
extern "C" void kernel_launch(void* const* d_in, const int* in_sizes, int n_in,
                              void* d_out, int out_size)
{
    const float* f0   = (const float*)d_in[0];
    const float* f1   = (const float*)d_in[1];
    const float* refs = (const float*)d_in[2];
    const float* intr = (const float*)d_in[3];
    const float* extr = (const float*)d_in[4];
    const float* qin  = (const float*)d_in[5];
    const float* Wq   = (const float*)d_in[6];
    const float* bq   = (const float*)d_in[7];
    const float* Wk   = (const float*)d_in[8];
    const float* bk   = (const float*)d_in[9];
    const float* Wv   = (const float*)d_in[10];
    const float* bv   = (const float*)d_in[11];
    const float* Wo   = (const float*)d_in[12];
    const float* bo   = (const float*)d_in[13];
    float* out = (float*)d_out;

    float *p_ctx, *p_q, *p_k, *p_v, *p_o;
    cudaGetSymbolAddress((void**)&p_ctx, g_ctx);
    cudaGetSymbolAddress((void**)&p_q,   g_q);
    cudaGetSymbolAddress((void**)&p_k,   g_k);
    cudaGetSymbolAddress((void**)&p_v,   g_v);
    cudaGetSymbolAddress((void**)&p_o,   g_o);

    sampler_kernel<<<dim3(NQ, NB), 256>>>(f0, f1, refs, intr, extr);

    dim3 ggrid(4, (NM + 63)/64);
    gemm_nt_kernel<<<ggrid, 256>>>(qin,   Wq, bq, p_q, NM);
    gemm_nt_kernel<<<ggrid, 256>>>(p_ctx, Wk, bk, p_k, NM);
    gemm_nt_kernel<<<ggrid, 256>>>(p_ctx, Wv, bv, p_v, NM);

    attn_kernel<<<dim3((NQ + 31)/32, NH, NB), 128>>>(p_q, p_k, p_v, p_o);

    gemm_nt_kernel<<<ggrid, 256>>>(p_o, Wo, bo, out, NM);
}

// round 3
// speedup vs baseline: 1.0974x; 1.0974x over previous
#include <cuda_runtime.h>
#include <math.h>

#define NB 2
#define NV 6
#define NC 256
#define NQ 900
#define NM (NB*NQ)       // 1800 rows
#define NH 8
#define HDIM 32

#define NEG_INF (__int_as_float(0xff800000))

// Scratch (no allocations allowed)
__device__ float g_ctx[NM*NC];
__device__ float g_q[NM*NC];
__device__ float g_k[NM*NC];
__device__ float g_v[NM*NC];
__device__ float g_o[NM*NC];

// ---------------------------------------------------------------------------
// Sampler: one block per (b,q). 48 projections (2 levels x 6 views x 4 kps)
// set up by threads 0..47; then 256 threads (one per channel) gather only
// in-bounds taps. Validity count (z>0) matches reference exactly.
// ---------------------------------------------------------------------------
__global__ __launch_bounds__(256) void sampler_kernel(
    const float* __restrict__ f0, const float* __restrict__ f1,
    const float* __restrict__ refs, const float* __restrict__ intr,
    const float* __restrict__ extr)
{
    const int q = blockIdx.x, b = blockIdx.y;
    __shared__ int   s_off[48][4];
    __shared__ float s_w[48][4];
    __shared__ int   s_valid[48];
    __shared__ int   s_any[48];
    const int t = threadIdx.x;

    if (t < 48) {
        const int lvl = t / 24, rem = t % 24, v = rem >> 2, kp = rem & 3;
        const float kxs[4] = {0.f, 2.f, 0.f, -2.f};
        const float kys[4] = {0.f, 0.f, 2.f, 0.f};
        const float* rp = refs + ((size_t)b*NQ + q)*3;
        float px = rp[0] + kxs[kp], py = rp[1] + kys[kp], pz = rp[2];
        const float* E = extr + ((size_t)b*NV + v)*16;
        float cx = E[0]*px + E[1]*py + E[2]*pz  + E[3];
        float cy = E[4]*px + E[5]*py + E[6]*pz  + E[7];
        float cz = E[8]*px + E[9]*py + E[10]*pz + E[11];
        const float* I = intr + ((size_t)b*NV + v)*9;
        float u  = I[0]*cx + I[1]*cy + I[2]*cz;
        float vv = I[3]*cx + I[4]*cy + I[5]*cz;
        float w  = I[6]*cx + I[7]*cy + I[8]*cz;
        float zs = (fabsf(w) > 1e-6f) ? w : 1e-6f;
        const int Wd = lvl ? 88 : 176, Hd = lvl ? 32 : 64;
        // replicate reference's normalize->denormalize round trip exactly
        float gx = 2.f*(u/zs)/(float)(Wd-1) - 1.f;
        float gy = 2.f*(vv/zs)/(float)(Hd-1) - 1.f;
        float x = (gx + 1.f)*0.5f*(float)(Wd-1);
        float y = (gy + 1.f)*0.5f*(float)(Hd-1);
        float x0 = floorf(x), y0 = floorf(y);
        float wx1 = x - x0, wx0 = 1.f - wx1;
        float wy1 = y - y0, wy0 = 1.f - wy1;
        const int valid = (w > 0.f) ? 1 : 0;
        s_valid[t] = valid;
        int any = 0;
        #pragma unroll
        for (int ti = 0; ti < 4; ti++) {
            float xi = (ti & 1) ? x0 + 1.f : x0;
            float yi = (ti & 2) ? y0 + 1.f : y0;
            float wt = ((ti & 1) ? wx1 : wx0) * ((ti & 2) ? wy1 : wy0);
            bool inb = (xi >= 0.f) && (xi <= (float)(Wd-1)) &&
                       (yi >= 0.f) && (yi <= (float)(Hd-1));
            if (valid && inb && wt != 0.f) {
                s_off[t][ti] = (int)yi * Wd + (int)xi;
                s_w[t][ti]   = wt;
                any = 1;
            } else {
                s_off[t][ti] = -1;
            }
        }
        s_any[t] = any;
    }
    __syncthreads();

    float acc0 = 0.f, acc1 = 0.f;
    for (int p = 0; p < 48; p++) {
        if (!s_any[p]) continue;
        const int lvl = (p >= 24) ? 1 : 0;
        const int rem = p - lvl*24, v = rem >> 2;
        const float* fb = lvl ? f1 + ((size_t)((b*NV + v)*NC + t))*(32*88)
                              : f0 + ((size_t)((b*NV + v)*NC + t))*(64*176);
        float a = 0.f;
        #pragma unroll
        for (int ti = 0; ti < 4; ti++) {
            int off = s_off[p][ti];
            if (off >= 0) a += s_w[p][ti] * __ldg(fb + off);
        }
        if (lvl) acc1 += a; else acc0 += a;
    }
    int cnt0 = 0, cnt1 = 0;
    #pragma unroll
    for (int p = 0; p < 24; p++) cnt0 += s_valid[p];
    #pragma unroll
    for (int p = 24; p < 48; p++) cnt1 += s_valid[p];
    float r = 0.5f * (acc0 / fmaxf((float)cnt0, 1.f) +
                      acc1 / fmaxf((float)cnt1, 1.f));
    g_ctx[((size_t)b*NQ + q)*NC + t] = r;
}

// ---------------------------------------------------------------------------
// Double-buffered GEMM core (NT): C[M,256] = A[M,256]*W[256,256]^T + bias.
// 64x64 tile, BK=16, 256 threads, 4x4 micro-tile, 1 sync per k-tile.
// ---------------------------------------------------------------------------
__device__ __forceinline__ void gemm_tile_core(
    const float* __restrict__ A, const float* __restrict__ Wm,
    const float* __restrict__ bias, float* __restrict__ C,
    int M, int m0, int n0)
{
    const int K = 256, N = 256;
    __shared__ float As[2][16][64];
    __shared__ float Ws[2][16][64];
    const int t = threadIdx.x;
    const int tx = t & 15, ty = t >> 4;
    const int lr = t >> 2, ls = t & 3;
    const bool arow = (m0 + lr < M);
    const float* Aptr = A + (size_t)(m0 + lr)*K + ls*4;
    const float* Wptr = Wm + (size_t)(n0 + lr)*K + ls*4;

    float acc[4][4] = {};

    // preload k-tile 0
    float4 av = arow ? *(const float4*)(Aptr) : make_float4(0.f,0.f,0.f,0.f);
    float4 wv = *(const float4*)(Wptr);
    As[0][ls*4+0][lr] = av.x; As[0][ls*4+1][lr] = av.y;
    As[0][ls*4+2][lr] = av.z; As[0][ls*4+3][lr] = av.w;
    Ws[0][ls*4+0][lr] = wv.x; Ws[0][ls*4+1][lr] = wv.y;
    Ws[0][ls*4+2][lr] = wv.z; Ws[0][ls*4+3][lr] = wv.w;
    __syncthreads();

    const int NT = K / 16;   // 16
    #pragma unroll 1
    for (int kt = 0; kt < NT; kt++) {
        const int cur = kt & 1;
        float4 anx, wnx;
        if (kt + 1 < NT) {
            const int k0 = (kt + 1) * 16;
            anx = arow ? *(const float4*)(Aptr + k0) : make_float4(0.f,0.f,0.f,0.f);
            wnx = *(const float4*)(Wptr + k0);
        }
        #pragma unroll
        for (int kk = 0; kk < 16; kk++) {
            float a[4], w[4];
            *(float4*)a = *(const float4*)&As[cur][kk][ty*4];
            *(float4*)w = *(const float4*)&Ws[cur][kk][tx*4];
            #pragma unroll
            for (int i = 0; i < 4; i++)
                #pragma unroll
                for (int j = 0; j < 4; j++)
                    acc[i][j] += a[i]*w[j];
        }
        if (kt + 1 < NT) {
            const int nxt = cur ^ 1;
            As[nxt][ls*4+0][lr] = anx.x; As[nxt][ls*4+1][lr] = anx.y;
            As[nxt][ls*4+2][lr] = anx.z; As[nxt][ls*4+3][lr] = anx.w;
            Ws[nxt][ls*4+0][lr] = wnx.x; Ws[nxt][ls*4+1][lr] = wnx.y;
            Ws[nxt][ls*4+2][lr] = wnx.z; Ws[nxt][ls*4+3][lr] = wnx.w;
            __syncthreads();
        }
    }

    float4 bv4 = *(const float4*)(bias + n0 + tx*4);
    #pragma unroll
    for (int i = 0; i < 4; i++) {
        int m = m0 + ty*4 + i;
        if (m >= M) continue;
        float4 r;
        r.x = acc[i][0] + bv4.x;
        r.y = acc[i][1] + bv4.y;
        r.z = acc[i][2] + bv4.z;
        r.w = acc[i][3] + bv4.w;
        *(float4*)(C + (size_t)m*N + n0 + tx*4) = r;
    }
}

// Fused Q/K/V projections: blockIdx.z selects {A, W, bias, C}
__global__ __launch_bounds__(256) void gemm_qkv_kernel(
    const float* __restrict__ qin, const float* __restrict__ ctx,
    const float* __restrict__ Wq, const float* __restrict__ bq,
    const float* __restrict__ Wk, const float* __restrict__ bk,
    const float* __restrict__ Wv, const float* __restrict__ bv,
    float* __restrict__ Cq, float* __restrict__ Ck, float* __restrict__ Cv)
{
    const int z = blockIdx.z;
    const float* A  = (z == 0) ? qin : ctx;
    const float* W  = (z == 0) ? Wq : (z == 1) ? Wk : Wv;
    const float* bi = (z == 0) ? bq : (z == 1) ? bk : bv;
    float* C        = (z == 0) ? Cq : (z == 1) ? Ck : Cv;
    gemm_tile_core(A, W, bi, C, NM, blockIdx.y * 64, blockIdx.x * 64);
}

__global__ __launch_bounds__(256) void gemm_nt_kernel(
    const float* __restrict__ A, const float* __restrict__ Wm,
    const float* __restrict__ bias, float* __restrict__ C, int M)
{
    gemm_tile_core(A, Wm, bias, C, M, blockIdx.y * 64, blockIdx.x * 64);
}

// ---------------------------------------------------------------------------
// Attention: block = 32 q-rows x 4 key-splits (128 thr). K/V staged in smem,
// 64-key tiles, per-tile max + single rescale (online softmax), then a
// 4-way split merge through shared memory.
// ---------------------------------------------------------------------------
__global__ __launch_bounds__(128) void attn_kernel(
    const float* __restrict__ gq, const float* __restrict__ gk,
    const float* __restrict__ gv, float* __restrict__ go)
{
    const int D = NC;
    const float scale = 0.17677669529663687f;   // 1/sqrt(32)
    const int b = blockIdx.z, h = blockIdx.y;
    const int m0 = blockIdx.x * 32;
    const int tid = threadIdx.x;
    const int lane = tid & 31, wrp = tid >> 5;
    const int m = m0 + lane;
    const bool act = (m < NQ);

    __shared__ float sk[64][32];
    __shared__ float sv[64][32];
    __shared__ float s_m[4][32];
    __shared__ float s_l[4][32];
    __shared__ float s_o[4][32][33];   // padded: conflict-free merge

    float qreg[HDIM];
    #pragma unroll
    for (int d = 0; d < HDIM; d++)
        qreg[d] = act ? gq[((size_t)(b*NQ + m))*D + h*HDIM + d] : 0.f;

    float mx = NEG_INF, l = 0.f;
    float o[HDIM];
    #pragma unroll
    for (int d = 0; d < HDIM; d++) o[d] = 0.f;

    for (int k0 = 0; k0 < NQ; k0 += 64) {
        const int kn = min(64, NQ - k0);
        __syncthreads();
        for (int i = tid; i < 512; i += 128) {
            int r = i >> 3, sg = i & 7;
            float4 kv = make_float4(0.f,0.f,0.f,0.f);
            float4 vv = make_float4(0.f,0.f,0.f,0.f);
            if (r < kn) {
                size_t base = ((size_t)(b*NQ + k0 + r))*D + h*HDIM + sg*4;
                kv = *(const float4*)(gk + base);
                vv = *(const float4*)(gv + base);
            }
            *(float4*)&sk[r][sg*4] = kv;
            *(float4*)&sv[r][sg*4] = vv;
        }
        __syncthreads();

        float sc[16];
        float tmax = NEG_INF;
        #pragma unroll
        for (int jj = 0; jj < 16; jj++) {
            int j = wrp*16 + jj;
            float s;
            if (j < kn) {
                s = 0.f;
                #pragma unroll
                for (int d = 0; d < HDIM; d++) s += qreg[d]*sk[j][d];
                s *= scale;
            } else {
                s = NEG_INF;
            }
            sc[jj] = s;
            tmax = fmaxf(tmax, s);
        }
        float mnew = fmaxf(mx, tmax);
        float corr = __expf(mx - mnew);       // exp(-inf)=0 on first tile
        l *= corr;
        #pragma unroll
        for (int d = 0; d < HDIM; d++) o[d] *= corr;
        #pragma unroll
        for (int jj = 0; jj < 16; jj++) {
            int j = wrp*16 + jj;
            float p = __expf(sc[jj] - mnew);
            l += p;
            #pragma unroll
            for (int d = 0; d < HDIM; d++) o[d] += p * sv[j][d];
        }
        mx = mnew;
    }

    // merge the 4 key-splits
    s_m[wrp][lane] = mx;
    s_l[wrp][lane] = l;
    #pragma unroll
    for (int d = 0; d < HDIM; d++) s_o[wrp][lane][d] = o[d];
    __syncthreads();

    if (wrp == 0 && act) {
        float M2 = s_m[0][lane];
        #pragma unroll
        for (int s = 1; s < 4; s++) M2 = fmaxf(M2, s_m[s][lane]);
        float L = 0.f;
        float out[HDIM];
        #pragma unroll
        for (int d = 0; d < HDIM; d++) out[d] = 0.f;
        #pragma unroll
        for (int s = 0; s < 4; s++) {
            float w = __expf(s_m[s][lane] - M2);
            L += s_l[s][lane] * w;
            #pragma unroll
            for (int d = 0; d < HDIM; d++) out[d] += w * s_o[s][lane][d];
        }
        float invL = 1.f / L;
        #pragma unroll
        for (int d = 0; d < HDIM; d++)
            go[((size_t)(b*NQ + m))*D + h*HDIM + d] = out[d] * invL;
    }
}

// ---------------------------------------------------------------------------
extern "C" void kernel_launch(void* const* d_in, const int* in_sizes, int n_in,
                              void* d_out, int out_size)
{
    const float* f0   = (const float*)d_in[0];
    const float* f1   = (const float*)d_in[1];
    const float* refs = (const float*)d_in[2];
    const float* intr = (const float*)d_in[3];
    const float* extr = (const float*)d_in[4];
    const float* qin  = (const float*)d_in[5];
    const float* Wq   = (const float*)d_in[6];
    const float* bq   = (const float*)d_in[7];
    const float* Wk   = (const float*)d_in[8];
    const float* bk   = (const float*)d_in[9];
    const float* Wv   = (const float*)d_in[10];
    const float* bv   = (const float*)d_in[11];
    const float* Wo   = (const float*)d_in[12];
    const float* bo   = (const float*)d_in[13];
    float* out = (float*)d_out;

    float *p_ctx, *p_q, *p_k, *p_v, *p_o;
    cudaGetSymbolAddress((void**)&p_ctx, g_ctx);
    cudaGetSymbolAddress((void**)&p_q,   g_q);
    cudaGetSymbolAddress((void**)&p_k,   g_k);
    cudaGetSymbolAddress((void**)&p_v,   g_v);
    cudaGetSymbolAddress((void**)&p_o,   g_o);

    sampler_kernel<<<dim3(NQ, NB), 256>>>(f0, f1, refs, intr, extr);

    dim3 qkvgrid(4, (NM + 63)/64, 3);
    gemm_qkv_kernel<<<qkvgrid, 256>>>(qin, p_ctx, Wq, bq, Wk, bk, Wv, bv,
                                      p_q, p_k, p_v);

    attn_kernel<<<dim3((NQ + 31)/32, NH, NB), 128>>>(p_q, p_k, p_v, p_o);

    dim3 ggrid(4, (NM + 63)/64);
    gemm_nt_kernel<<<ggrid, 256>>>(p_o, Wo, bo, out, NM);
}